// round 8
// baseline (speedup 1.0000x reference)
#include <cuda_runtime.h>
#include <cstdint>

// ---------------------------------------------------------------------------
// SINDy layer: out[b, c] = sum_t Theta(z[b])[t] * (Xi*mask)[t, c]
// B=65536, Z=32, terms = 1 + 32 + 528 + 5984 = 6545, out fp32 [65536, 32].
//
// R6/R7 design: column-split FFMA2 GEMV.
//  - 128-thread CTA = 2 column groups x 64 threads; each thread: 2 rows x 16 cols
//    -> 16 packed f32x2 accumulators, 16 FFMA2 + 4 LDS.128 per term (4:1).
//  - grid 512 (128 rows/CTA) -> ~16 warps/SM resident (4/SMSP) for latency hiding.
//  - Xi_eff premasked to __device__ global, streamed via cp.async double buffer
//    (64-term / 8 KB chunks); all consume-side loads are plain C++ so ptxas can
//    software-pipeline across terms.
// (Round 6 bench was an infra failure; this is the same design re-submitted.)
// ---------------------------------------------------------------------------

#define ZDIM 32
#define NT 6545
#define CHUNK 64
#define NCH ((NT + CHUNK - 1) / CHUNK)   // 103
#define XI_BUF 8192                      // 64 terms * 128 B
#define ROWS 128
#define THREADS 128

__device__ __align__(16) float g_xi_eff[NT * ZDIM];

// ---------------- PTX helpers (non-volatile: ptxas may schedule freely) ----
#define FMA2(d, a, b, c) \
    asm("fma.rn.f32x2 %0, %1, %2, %3;" : "=l"(d) : "l"(a), "l"(b), "l"(c))
#define PACK2(d, s) \
    asm("mov.b64 %0, {%1, %1};" : "=l"(d) : "r"(s))
#define UNPACK2(x, y, p) \
    asm("mov.b64 {%0, %1}, %2;" : "=f"(x), "=f"(y) : "l"(p))

#define CP_ASYNC16(dst_u32, src_ptr) \
    asm volatile("cp.async.cg.shared.global [%0], [%1], 16;" \
                 :: "r"(dst_u32), "l"(src_ptr) : "memory")
#define CP_COMMIT() asm volatile("cp.async.commit_group;" ::: "memory")
#define CP_WAIT(N)  asm volatile("cp.async.wait_group %0;" :: "n"(N) : "memory")

// Stage one 64-term (8 KB) Xi chunk into SMEM buffer (c&1). 4 x 16B per thread.
#define STAGE(c) do {                                                        \
    uint32_t _dst = sbase + (((c) & 1) ? (uint32_t)XI_BUF : 0u);             \
    int _b4 = (c) * (CHUNK * 8);      /* float4 index of chunk start */      \
    const float4* _src = (const float4*)g_xi_eff;                            \
    _Pragma("unroll")                                                        \
    for (int _u = 0; _u < 4; _u++) {                                         \
        int _q = _u * THREADS + tid;                                         \
        int _g = _b4 + _q;                                                   \
        if (_g < NT * 8) CP_ASYNC16(_dst + 16u * (uint32_t)_q, _src + _g);   \
    }                                                                        \
    CP_COMMIT();                                                             \
} while (0)

// One polynomial term: this group's 16 Xi floats (warp-uniform LDS broadcast)
// FMA'd into both rows' 8 packed accumulators each; then advance the stream,
// swapping 64-term chunks on a block-uniform branch.
#define XI_TERM(th0, th1) do {                                               \
    ulonglong2 _q0 = xip[0], _q1 = xip[1], _q2 = xip[2], _q3 = xip[3];       \
    unsigned long long _t0, _t1;                                             \
    PACK2(_t0, __float_as_uint(th0));                                        \
    PACK2(_t1, __float_as_uint(th1));                                        \
    FMA2(acc0[0], _t0, _q0.x, acc0[0]); FMA2(acc1[0], _t1, _q0.x, acc1[0]);  \
    FMA2(acc0[1], _t0, _q0.y, acc0[1]); FMA2(acc1[1], _t1, _q0.y, acc1[1]);  \
    FMA2(acc0[2], _t0, _q1.x, acc0[2]); FMA2(acc1[2], _t1, _q1.x, acc1[2]);  \
    FMA2(acc0[3], _t0, _q1.y, acc0[3]); FMA2(acc1[3], _t1, _q1.y, acc1[3]);  \
    FMA2(acc0[4], _t0, _q2.x, acc0[4]); FMA2(acc1[4], _t1, _q2.x, acc1[4]);  \
    FMA2(acc0[5], _t0, _q2.y, acc0[5]); FMA2(acc1[5], _t1, _q2.y, acc1[5]);  \
    FMA2(acc0[6], _t0, _q3.x, acc0[6]); FMA2(acc1[6], _t1, _q3.x, acc1[6]);  \
    FMA2(acc0[7], _t0, _q3.y, acc0[7]); FMA2(acc1[7], _t1, _q3.y, acc1[7]);  \
    if (--rem == 0) {                 /* uniform across the block */         \
        __syncthreads();                                                     \
        ++ch;                                                                \
        if (ch + 1 < NCH) { STAGE(ch + 1); CP_WAIT(1); }                     \
        else              { CP_WAIT(0); }                                    \
        __syncthreads();                                                     \
        xip = (const ulonglong2*)(smem + ((ch & 1) ? XI_BUF : 0) + g * 64);  \
        rem = CHUNK;                                                         \
    } else {                                                                 \
        xip += 8;                                                            \
    }                                                                        \
} while (0)

// ---------------- prep: Xi_eff = Xi * Xi_mask ----------------
__global__ void prep_kernel(const float* __restrict__ Xi,
                            const float* __restrict__ mask) {
    int i = blockIdx.x * blockDim.x + threadIdx.x;
    if (i < NT * ZDIM) g_xi_eff[i] = Xi[i] * mask[i];
}

// ---------------- main kernel ----------------
__global__ void __launch_bounds__(THREADS, 4)
sindy_kernel(const float* __restrict__ z, float* __restrict__ out) {
    __shared__ __align__(16) char smem[2 * XI_BUF + ROWS * ZDIM * 4];  // 32 KB
    float* zsm = (float*)(smem + 2 * XI_BUF);   // [k][r]: zsm[k*128 + r]
    const int tid = threadIdx.x;
    const int cta = blockIdx.x;
    const int g   = tid >> 6;       // column group: cols [g*16, g*16+16)
    const int l   = tid & 63;       // row lane: rows l and l+64
    const uint32_t sbase = (uint32_t)__cvta_generic_to_shared(smem);

    // Kick off Xi chunk prefetches first (overlap with z staging).
    STAGE(0);
    STAGE(1);

    // Stage z rows [cta*128, cta*128+128) transposed: thread t stages row t
    // (conflict-free stores: lanes hit distinct banks at zsm[k*128 + t]).
    {
        const float4* zr = (const float4*)z + ((size_t)cta * ROWS + tid) * (ZDIM / 4);
        #pragma unroll
        for (int u = 0; u < 8; u++) {
            float4 v = zr[u];
            zsm[(u * 4 + 0) * ROWS + tid] = v.x;
            zsm[(u * 4 + 1) * ROWS + tid] = v.y;
            zsm[(u * 4 + 2) * ROWS + tid] = v.z;
            zsm[(u * 4 + 3) * ROWS + tid] = v.w;
        }
    }

    CP_WAIT(1);        // chunk 0 resident
    __syncthreads();   // z + chunk0 visible

    unsigned long long acc0[8], acc1[8];
    #pragma unroll
    for (int m = 0; m < 8; m++) { acc0[m] = 0ull; acc1[m] = 0ull; }

    const ulonglong2* xip = (const ulonglong2*)(smem + g * 64);
    int rem = CHUNK;
    int ch = 0;

    const float* zp = zsm + l;   // z(k, row0) = zp[k*128]; z(k, row1) = zp[k*128 + 64]

    // ---- term stream, exactly matching Xi row order ----
    // bias
    XI_TERM(1.0f, 1.0f);
    // linear: k = 0..31
    #pragma unroll 1
    for (int k = 0; k < ZDIM; k++) {
        XI_TERM(zp[k * 128], zp[k * 128 + 64]);
    }
    // quadratic: i <= k  (theta = z_i * z_k)
    #pragma unroll 1
    for (int i = 0; i < ZDIM; i++) {
        float a0 = zp[i * 128], a1 = zp[i * 128 + 64];
        #pragma unroll 2
        for (int k = i; k < ZDIM; k++) {
            XI_TERM(a0 * zp[k * 128], a1 * zp[k * 128 + 64]);
        }
    }
    // cubic: i <= j <= k  (theta = z_i * z_j * z_k, pair product hoisted)
    #pragma unroll 1
    for (int i = 0; i < ZDIM; i++) {
        float a0 = zp[i * 128], a1 = zp[i * 128 + 64];
        #pragma unroll 1
        for (int j = i; j < ZDIM; j++) {
            float p0 = a0 * zp[j * 128], p1 = a1 * zp[j * 128 + 64];
            #pragma unroll 2
            for (int k = j; k < ZDIM; k++) {
                XI_TERM(p0 * zp[k * 128], p1 * zp[k * 128 + 64]);
            }
        }
    }

    // ---- epilogue: write 2 rows x 16 cols ----
    size_t row0 = (size_t)cta * ROWS + l;
    float4* o0 = (float4*)(out + row0 * ZDIM + g * 16);
    float4* o1 = (float4*)(out + (row0 + 64) * ZDIM + g * 16);
    #pragma unroll
    for (int q = 0; q < 4; q++) {
        float4 v;
        UNPACK2(v.x, v.y, acc0[2 * q]);
        UNPACK2(v.z, v.w, acc0[2 * q + 1]);
        o0[q] = v;
    }
    #pragma unroll
    for (int q = 0; q < 4; q++) {
        float4 v;
        UNPACK2(v.x, v.y, acc1[2 * q]);
        UNPACK2(v.z, v.w, acc1[2 * q + 1]);
        o1[q] = v;
    }
}

// ---------------- launch ----------------
extern "C" void kernel_launch(void* const* d_in, const int* in_sizes, int n_in,
                              void* d_out, int out_size) {
    (void)in_sizes; (void)n_in; (void)out_size;
    const float* z    = (const float*)d_in[0];  // [65536, 32]
    const float* Xi   = (const float*)d_in[1];  // [6545, 32]
    const float* mask = (const float*)d_in[2];  // [6545, 32]
    // d_in[3] (z_mean) and d_in[4] (z_std) are unused by the reference.
    float* out = (float*)d_out;                 // [65536, 32]

    prep_kernel<<<(NT * ZDIM + 255) / 256, 256>>>(Xi, mask);
    sindy_kernel<<<65536 / ROWS, THREADS>>>(z, out);
}

// round 9
// speedup vs baseline: 1.9541x; 1.9541x over previous
#include <cuda_runtime.h>
#include <cstdint>

// ---------------------------------------------------------------------------
// SINDy layer: out[b, c] = sum_t Theta(z[b])[t] * (Xi*mask)[t, c]
// B=65536, Z=32, terms = 1 + 32 + 528 + 5984 = 6545 (padded to 6656).
//
// R9 design: branch-free index-table FFMA2 GEMV.
//  - Every term is uniformly theta_t = z[a]*z[b]*z[c] via idx table + sentinel
//    row z[32]=1.0  -> constant-trip inner loop, NO branch, ptxas pipelines.
//  - Thread = 2 rows x 32 cols: 32 FFMA2 + 2 MUL2 (packed f32x2) per term.
//  - 128 thr/CTA, 256 rows/CTA, grid 256, 2 CTA/SM.
//  - Xi_eff + idx streamed via cp.async double buffer (256-term chunks).
// ---------------------------------------------------------------------------

#define ZDIM 32
#define NT 6545
#define NTP 6656                       // padded: 26 * 256
#define CHUNK 256
#define NCH 26
#define XI_BUF 32768                   // 256 terms * 128 B
#define IDX_BUF 1024                   // 256 terms * 4 B
#define ROWS 256
#define THREADS 128

// SMEM layout (dynamic): [xi0][xi1][idx0][idx1][z: 33 x 128 x float2]
#define OFF_XI0  0
#define OFF_XI1  32768
#define OFF_IDX  65536                 // + buf*1024
#define OFF_Z    67584
#define SMEM_TOTAL (67584 + 33 * 128 * 8)   // 101376

__device__ __align__(16) float    g_xi_eff[NTP * ZDIM];
__device__ __align__(16) unsigned g_idx[NTP];

// ---------------- PTX helpers (non-volatile: ptxas schedules freely) -------
#define FMA2(d, a, b, c) \
    asm("fma.rn.f32x2 %0, %1, %2, %3;" : "=l"(d) : "l"(a), "l"(b), "l"(c))
#define MUL2(d, a, b) \
    asm("mul.rn.f32x2 %0, %1, %2;" : "=l"(d) : "l"(a), "l"(b))
#define PACK2(d, s) \
    asm("mov.b64 %0, {%1, %1};" : "=l"(d) : "r"(s))
#define SPLIT2(lo, hi, p) \
    asm("mov.b64 {%0, %1}, %2;" : "=r"(lo), "=r"(hi) : "l"(p))
#define UNPACK2(x, y, p) \
    asm("mov.b64 {%0, %1}, %2;" : "=f"(x), "=f"(y) : "l"(p))

#define CP_ASYNC16(dst_u32, src_ptr) \
    asm volatile("cp.async.cg.shared.global [%0], [%1], 16;" \
                 :: "r"(dst_u32), "l"(src_ptr) : "memory")
#define CP_COMMIT() asm volatile("cp.async.commit_group;" ::: "memory")
#define CP_WAIT(N)  asm volatile("cp.async.wait_group %0;" :: "n"(N) : "memory")

// Stage chunk c (Xi 32 KB + idx 1 KB) into buffer (c&1). One commit group.
#define STAGE(c) do {                                                        \
    int _buf = (c) & 1;                                                      \
    uint32_t _dx = sbase + (_buf ? (uint32_t)OFF_XI1 : (uint32_t)OFF_XI0);   \
    const float4* _xs = (const float4*)g_xi_eff + (c) * (CHUNK * 8);         \
    _Pragma("unroll")                                                        \
    for (int _u = 0; _u < 16; _u++) {                                        \
        int _q = _u * THREADS + tid;                                         \
        CP_ASYNC16(_dx + 16u * (uint32_t)_q, _xs + _q);                      \
    }                                                                        \
    if (tid < 64) {                                                          \
        const float4* _is = (const float4*)g_idx + (c) * 64 + tid;           \
        CP_ASYNC16(sbase + (uint32_t)OFF_IDX + (uint32_t)(_buf * IDX_BUF)    \
                   + 16u * (uint32_t)tid, _is);                              \
    }                                                                        \
    CP_COMMIT();                                                             \
} while (0)

// ---------------- init kernels (run each replay; ~5 us total) --------------
__global__ void prep_xi_kernel(const float* __restrict__ Xi,
                               const float* __restrict__ mask) {
    int i = blockIdx.x * blockDim.x + threadIdx.x;
    if (i < NTP * ZDIM) g_xi_eff[i] = (i < NT * ZDIM) ? Xi[i] * mask[i] : 0.f;
}

__global__ void build_idx_kernel() {
    int t = threadIdx.x;   // 64 threads, 1 block
    if (t < 32) {
        int i = t;
        // quadratic block: rows with first index i start at 33 + 32i - i(i-1)/2
        int pos = 33 + 32 * i - (i * (i - 1)) / 2;
        for (int j = i; j < 32; j++)
            g_idx[pos++] = (unsigned)i | ((unsigned)j << 8) | (32u << 16);
        // cubic block start for first index i
        int cpos = 561;
        for (int a = 0; a < i; a++) cpos += ((32 - a) * (33 - a)) / 2;
        for (int j = i; j < 32; j++)
            for (int k = j; k < 32; k++)
                g_idx[cpos++] = (unsigned)i | ((unsigned)j << 8) | ((unsigned)k << 16);
    } else if (t == 32) {
        g_idx[0] = 32u | (32u << 8) | (32u << 16);          // bias: 1*1*1
        for (int k = 0; k < 32; k++)                         // linear
            g_idx[1 + k] = (unsigned)k | (32u << 8) | (32u << 16);
    } else {
        // pad tail [6545, 6656): theta=1, xi=0 -> no contribution
        for (int p = NT + (t - 33); p < NTP; p += 31)
            g_idx[p] = 32u | (32u << 8) | (32u << 16);
    }
}

// ---------------- main kernel ----------------------------------------------
__global__ void __launch_bounds__(THREADS, 2)
sindy_kernel(const float* __restrict__ z, float* __restrict__ out) {
    extern __shared__ __align__(16) char smem[];
    const int tid = threadIdx.x;
    const int cta = blockIdx.x;
    const uint32_t sbase = (uint32_t)__cvta_generic_to_shared(smem);

    // Prefetch first two Xi/idx chunks (overlaps z staging).
    STAGE(0);
    STAGE(1);

    // Stage z as packed row-pairs: zz[a*128 + l] = (z[base+l][a], z[base+128+l][a]),
    // plus sentinel row a=32 of (1,1). Thread t owns rows t and t+128.
    {
        float* zs = (float*)(smem + OFF_Z);
        const float4* r0 = (const float4*)z + ((size_t)cta * ROWS + tid) * 8;
        const float4* r1 = r0 + 128 * 8;
        #pragma unroll
        for (int u = 0; u < 8; u++) {
            float4 a = r0[u];
            float4 b = r1[u];
            float2* zp = (float2*)zs;
            zp[(u * 4 + 0) * 128 + tid] = make_float2(a.x, b.x);
            zp[(u * 4 + 1) * 128 + tid] = make_float2(a.y, b.y);
            zp[(u * 4 + 2) * 128 + tid] = make_float2(a.z, b.z);
            zp[(u * 4 + 3) * 128 + tid] = make_float2(a.w, b.w);
        }
        ((float2*)zs)[32 * 128 + tid] = make_float2(1.f, 1.f);
    }

    CP_WAIT(1);        // chunk 0 resident
    __syncthreads();   // z + chunk 0 visible

    unsigned long long acc0[16], acc1[16];
    #pragma unroll
    for (int m = 0; m < 16; m++) { acc0[m] = 0ull; acc1[m] = 0ull; }

    const unsigned long long* zz =
        (const unsigned long long*)(smem + OFF_Z) + tid;

    for (int ch = 0; ch < NCH; ch++) {
        const int buf = ch & 1;
        const ulonglong2* xb =
            (const ulonglong2*)(smem + (buf ? OFF_XI1 : OFF_XI0));
        const unsigned* idxp = (const unsigned*)(smem + OFF_IDX + buf * IDX_BUF);

        #pragma unroll 2
        for (int t = 0; t < CHUNK; t++) {
            unsigned p = idxp[t];
            unsigned long long za = zz[(p & 255u) << 7];
            unsigned long long zb = zz[((p >> 8) & 255u) << 7];
            unsigned long long zc = zz[(p >> 16) << 7];
            unsigned long long th;
            MUL2(th, za, zb);
            MUL2(th, th, zc);
            unsigned lo, hi;
            SPLIT2(lo, hi, th);
            unsigned long long t00, t11;
            PACK2(t00, lo);
            PACK2(t11, hi);

            const ulonglong2* xt = xb + t * 8;
            ulonglong2 q0 = xt[0], q1 = xt[1], q2 = xt[2], q3 = xt[3];
            ulonglong2 q4 = xt[4], q5 = xt[5], q6 = xt[6], q7 = xt[7];

            FMA2(acc0[ 0], t00, q0.x, acc0[ 0]); FMA2(acc1[ 0], t11, q0.x, acc1[ 0]);
            FMA2(acc0[ 1], t00, q0.y, acc0[ 1]); FMA2(acc1[ 1], t11, q0.y, acc1[ 1]);
            FMA2(acc0[ 2], t00, q1.x, acc0[ 2]); FMA2(acc1[ 2], t11, q1.x, acc1[ 2]);
            FMA2(acc0[ 3], t00, q1.y, acc0[ 3]); FMA2(acc1[ 3], t11, q1.y, acc1[ 3]);
            FMA2(acc0[ 4], t00, q2.x, acc0[ 4]); FMA2(acc1[ 4], t11, q2.x, acc1[ 4]);
            FMA2(acc0[ 5], t00, q2.y, acc0[ 5]); FMA2(acc1[ 5], t11, q2.y, acc1[ 5]);
            FMA2(acc0[ 6], t00, q3.x, acc0[ 6]); FMA2(acc1[ 6], t11, q3.x, acc1[ 6]);
            FMA2(acc0[ 7], t00, q3.y, acc0[ 7]); FMA2(acc1[ 7], t11, q3.y, acc1[ 7]);
            FMA2(acc0[ 8], t00, q4.x, acc0[ 8]); FMA2(acc1[ 8], t11, q4.x, acc1[ 8]);
            FMA2(acc0[ 9], t00, q4.y, acc0[ 9]); FMA2(acc1[ 9], t11, q4.y, acc1[ 9]);
            FMA2(acc0[10], t00, q5.x, acc0[10]); FMA2(acc1[10], t11, q5.x, acc1[10]);
            FMA2(acc0[11], t00, q5.y, acc0[11]); FMA2(acc1[11], t11, q5.y, acc1[11]);
            FMA2(acc0[12], t00, q6.x, acc0[12]); FMA2(acc1[12], t11, q6.x, acc1[12]);
            FMA2(acc0[13], t00, q6.y, acc0[13]); FMA2(acc1[13], t11, q6.y, acc1[13]);
            FMA2(acc0[14], t00, q7.x, acc0[14]); FMA2(acc1[14], t11, q7.x, acc1[14]);
            FMA2(acc0[15], t00, q7.y, acc0[15]); FMA2(acc1[15], t11, q7.y, acc1[15]);
        }

        __syncthreads();                 // all warps done reading buf
        if (ch + 2 < NCH) {
            STAGE(ch + 2);               // refill the buffer just drained
            CP_WAIT(1);                  // chunk ch+1 complete
        } else {
            CP_WAIT(0);
        }
        __syncthreads();                 // staged data visible
    }

    // ---- epilogue: 2 rows x 32 cols per thread ----
    size_t r0 = (size_t)cta * ROWS + tid;
    float4* o0 = (float4*)(out + r0 * ZDIM);
    float4* o1 = (float4*)(out + (r0 + 128) * ZDIM);
    #pragma unroll
    for (int q = 0; q < 8; q++) {
        float4 v;
        UNPACK2(v.x, v.y, acc0[2 * q]);
        UNPACK2(v.z, v.w, acc0[2 * q + 1]);
        o0[q] = v;
    }
    #pragma unroll
    for (int q = 0; q < 8; q++) {
        float4 v;
        UNPACK2(v.x, v.y, acc1[2 * q]);
        UNPACK2(v.z, v.w, acc1[2 * q + 1]);
        o1[q] = v;
    }
}

// ---------------- launch ----------------------------------------------------
extern "C" void kernel_launch(void* const* d_in, const int* in_sizes, int n_in,
                              void* d_out, int out_size) {
    (void)in_sizes; (void)n_in; (void)out_size;
    const float* z    = (const float*)d_in[0];  // [65536, 32]
    const float* Xi   = (const float*)d_in[1];  // [6545, 32]
    const float* mask = (const float*)d_in[2];  // [6545, 32]
    // d_in[3] (z_mean) and d_in[4] (z_std) are unused by the reference.
    float* out = (float*)d_out;                 // [65536, 32]

    prep_xi_kernel<<<(NTP * ZDIM + 255) / 256, 256>>>(Xi, mask);
    build_idx_kernel<<<1, 64>>>();

    (void)cudaFuncSetAttribute(sindy_kernel,
                               cudaFuncAttributeMaxDynamicSharedMemorySize,
                               SMEM_TOTAL);
    sindy_kernel<<<65536 / ROWS, THREADS, SMEM_TOTAL>>>(z, out);
}

// round 10
// speedup vs baseline: 2.0126x; 1.0299x over previous
#include <cuda_runtime.h>
#include <cstdint>

// ---------------------------------------------------------------------------
// SINDy layer: out[b, c] = sum_t Theta(z[b])[t] * (Xi*mask)[t, c]
// B=65536, Z=32, terms = 1 + 32 + 528 + 5984 = 6545 (padded to 6656).
//
// R10 design = R9 (branch-free index-table FFMA2 GEMV) + explicit software
// pipelining of the theta operand loads one term ahead, so the
// idx->z-LDS->MUL2 chain overlaps the previous term's 32-FFMA2 block.
//  - Thread = 2 rows x 32 cols: 32 FFMA2 + 2 MUL2 (packed f32x2) per term.
//  - 128 thr/CTA, 256 rows/CTA, grid 256, 2 CTA/SM.
//  - Xi_eff + idx streamed via cp.async double buffer (256-term chunks).
//  - idx build folded into prep kernel (2 launches -> ncu lands on sindy).
// ---------------------------------------------------------------------------

#define ZDIM 32
#define NT 6545
#define NTP 6656                       // padded: 26 * 256
#define CHUNK 256
#define NCH 26
#define XI_BUF 32768                   // 256 terms * 128 B
#define IDX_BUF 1024                   // 256 terms * 4 B
#define ROWS 256
#define THREADS 128

// SMEM layout (dynamic): [xi0][xi1][idx0][idx1][z: 33 x 128 x float2]
#define OFF_XI0  0
#define OFF_XI1  32768
#define OFF_IDX  65536                 // + buf*1024
#define OFF_Z    67584
#define SMEM_TOTAL (67584 + 33 * 128 * 8)   // 101376

__device__ __align__(16) float    g_xi_eff[NTP * ZDIM];
__device__ __align__(16) unsigned g_idx[NTP];

// ---------------- PTX helpers (non-volatile: ptxas schedules freely) -------
#define FMA2(d, a, b, c) \
    asm("fma.rn.f32x2 %0, %1, %2, %3;" : "=l"(d) : "l"(a), "l"(b), "l"(c))
#define MUL2(d, a, b) \
    asm("mul.rn.f32x2 %0, %1, %2;" : "=l"(d) : "l"(a), "l"(b))
#define PACK2(d, s) \
    asm("mov.b64 %0, {%1, %1};" : "=l"(d) : "r"(s))
#define SPLIT2(lo, hi, p) \
    asm("mov.b64 {%0, %1}, %2;" : "=r"(lo), "=r"(hi) : "l"(p))
#define UNPACK2(x, y, p) \
    asm("mov.b64 {%0, %1}, %2;" : "=f"(x), "=f"(y) : "l"(p))

#define CP_ASYNC16(dst_u32, src_ptr) \
    asm volatile("cp.async.cg.shared.global [%0], [%1], 16;" \
                 :: "r"(dst_u32), "l"(src_ptr) : "memory")
#define CP_COMMIT() asm volatile("cp.async.commit_group;" ::: "memory")
#define CP_WAIT(N)  asm volatile("cp.async.wait_group %0;" :: "n"(N) : "memory")

// Stage chunk c (Xi 32 KB + idx 1 KB) into buffer (c&1). One commit group.
#define STAGE(c) do {                                                        \
    int _buf = (c) & 1;                                                      \
    uint32_t _dx = sbase + (_buf ? (uint32_t)OFF_XI1 : (uint32_t)OFF_XI0);   \
    const float4* _xs = (const float4*)g_xi_eff + (c) * (CHUNK * 8);         \
    _Pragma("unroll")                                                        \
    for (int _u = 0; _u < 16; _u++) {                                        \
        int _q = _u * THREADS + tid;                                         \
        CP_ASYNC16(_dx + 16u * (uint32_t)_q, _xs + _q);                      \
    }                                                                        \
    if (tid < 64) {                                                          \
        const float4* _is = (const float4*)g_idx + (c) * 64 + tid;           \
        CP_ASYNC16(sbase + (uint32_t)OFF_IDX + (uint32_t)(_buf * IDX_BUF)    \
                   + 16u * (uint32_t)tid, _is);                              \
    }                                                                        \
    CP_COMMIT();                                                             \
} while (0)

// ---------------- prep: Xi_eff = Xi * mask, plus idx table -----------------
__global__ void prep_kernel(const float* __restrict__ Xi,
                            const float* __restrict__ mask) {
    if (blockIdx.x < 832) {
        int i = blockIdx.x * 256 + threadIdx.x;
        if (i < NTP * ZDIM)
            g_xi_eff[i] = (i < NT * ZDIM) ? Xi[i] * mask[i] : 0.f;
        return;
    }
    // last block: build the monomial index table (verified in R9)
    int t = threadIdx.x;
    if (t >= 64) return;
    if (t < 32) {
        int i = t;
        int pos = 33 + 32 * i - (i * (i - 1)) / 2;          // quadratic rows
        for (int j = i; j < 32; j++)
            g_idx[pos++] = (unsigned)i | ((unsigned)j << 8) | (32u << 16);
        int cpos = 561;                                      // cubic rows
        for (int a = 0; a < i; a++) cpos += ((32 - a) * (33 - a)) / 2;
        for (int j = i; j < 32; j++)
            for (int k = j; k < 32; k++)
                g_idx[cpos++] = (unsigned)i | ((unsigned)j << 8) | ((unsigned)k << 16);
    } else if (t == 32) {
        g_idx[0] = 32u | (32u << 8) | (32u << 16);          // bias
        for (int k = 0; k < 32; k++)                         // linear
            g_idx[1 + k] = (unsigned)k | (32u << 8) | (32u << 16);
    } else {
        for (int p = NT + (t - 33); p < NTP; p += 31)        // pad tail
            g_idx[p] = 32u | (32u << 8) | (32u << 16);
    }
}

// ---------------- main kernel ----------------------------------------------
__global__ void __launch_bounds__(THREADS, 2)
sindy_kernel(const float* __restrict__ z, float* __restrict__ out) {
    extern __shared__ __align__(16) char smem[];
    const int tid = threadIdx.x;
    const int cta = blockIdx.x;
    const uint32_t sbase = (uint32_t)__cvta_generic_to_shared(smem);

    // Prefetch first two Xi/idx chunks (overlaps z staging).
    STAGE(0);
    STAGE(1);

    // Stage z as packed row-pairs: zz[a*128 + l] = (z[base+l][a], z[base+128+l][a]),
    // plus sentinel row a=32 of (1,1). Thread t owns rows t and t+128.
    {
        float* zs = (float*)(smem + OFF_Z);
        const float4* r0 = (const float4*)z + ((size_t)cta * ROWS + tid) * 8;
        const float4* r1 = r0 + 128 * 8;
        #pragma unroll
        for (int u = 0; u < 8; u++) {
            float4 a = r0[u];
            float4 b = r1[u];
            float2* zp = (float2*)zs;
            zp[(u * 4 + 0) * 128 + tid] = make_float2(a.x, b.x);
            zp[(u * 4 + 1) * 128 + tid] = make_float2(a.y, b.y);
            zp[(u * 4 + 2) * 128 + tid] = make_float2(a.z, b.z);
            zp[(u * 4 + 3) * 128 + tid] = make_float2(a.w, b.w);
        }
        ((float2*)zs)[32 * 128 + tid] = make_float2(1.f, 1.f);
    }

    CP_WAIT(1);        // chunk 0 resident
    __syncthreads();   // z + chunk 0 visible

    unsigned long long acc0[16], acc1[16];
    #pragma unroll
    for (int m = 0; m < 16; m++) { acc0[m] = 0ull; acc1[m] = 0ull; }

    const unsigned long long* zz =
        (const unsigned long long*)(smem + OFF_Z) + tid;

    for (int ch = 0; ch < NCH; ch++) {
        const int buf = ch & 1;
        const ulonglong2* xb =
            (const ulonglong2*)(smem + (buf ? OFF_XI1 : OFF_XI0));
        const unsigned* idxp = (const unsigned*)(smem + OFF_IDX + buf * IDX_BUF);

        // ---- software pipeline: preload theta operands for term 0 ----
        unsigned p0 = idxp[0];
        unsigned long long za = zz[(p0 & 255u) << 7];
        unsigned long long zb = zz[((p0 >> 8) & 255u) << 7];
        unsigned long long zc = zz[(p0 >> 16) << 7];

        #pragma unroll 2
        for (int t = 0; t < CHUNK; t++) {
            // theta for current term (operands already in regs)
            unsigned long long th;
            MUL2(th, za, zb);
            MUL2(th, th, zc);

            // kick off next term's operand loads (wrap-masked, branch-free;
            // last iteration harmlessly re-reads term 0)
            unsigned pn = idxp[(t + 1) & (CHUNK - 1)];
            za = zz[(pn & 255u) << 7];
            zb = zz[((pn >> 8) & 255u) << 7];
            zc = zz[(pn >> 16) << 7];

            unsigned lo, hi;
            SPLIT2(lo, hi, th);
            unsigned long long t00, t11;
            PACK2(t00, lo);
            PACK2(t11, hi);

            const ulonglong2* xt = xb + t * 8;
            ulonglong2 q0 = xt[0], q1 = xt[1], q2 = xt[2], q3 = xt[3];
            ulonglong2 q4 = xt[4], q5 = xt[5], q6 = xt[6], q7 = xt[7];

            FMA2(acc0[ 0], t00, q0.x, acc0[ 0]); FMA2(acc1[ 0], t11, q0.x, acc1[ 0]);
            FMA2(acc0[ 1], t00, q0.y, acc0[ 1]); FMA2(acc1[ 1], t11, q0.y, acc1[ 1]);
            FMA2(acc0[ 2], t00, q1.x, acc0[ 2]); FMA2(acc1[ 2], t11, q1.x, acc1[ 2]);
            FMA2(acc0[ 3], t00, q1.y, acc0[ 3]); FMA2(acc1[ 3], t11, q1.y, acc1[ 3]);
            FMA2(acc0[ 4], t00, q2.x, acc0[ 4]); FMA2(acc1[ 4], t11, q2.x, acc1[ 4]);
            FMA2(acc0[ 5], t00, q2.y, acc0[ 5]); FMA2(acc1[ 5], t11, q2.y, acc1[ 5]);
            FMA2(acc0[ 6], t00, q3.x, acc0[ 6]); FMA2(acc1[ 6], t11, q3.x, acc1[ 6]);
            FMA2(acc0[ 7], t00, q3.y, acc0[ 7]); FMA2(acc1[ 7], t11, q3.y, acc1[ 7]);
            FMA2(acc0[ 8], t00, q4.x, acc0[ 8]); FMA2(acc1[ 8], t11, q4.x, acc1[ 8]);
            FMA2(acc0[ 9], t00, q4.y, acc0[ 9]); FMA2(acc1[ 9], t11, q4.y, acc1[ 9]);
            FMA2(acc0[10], t00, q5.x, acc0[10]); FMA2(acc1[10], t11, q5.x, acc1[10]);
            FMA2(acc0[11], t00, q5.y, acc0[11]); FMA2(acc1[11], t11, q5.y, acc1[11]);
            FMA2(acc0[12], t00, q6.x, acc0[12]); FMA2(acc1[12], t11, q6.x, acc1[12]);
            FMA2(acc0[13], t00, q6.y, acc0[13]); FMA2(acc1[13], t11, q6.y, acc1[13]);
            FMA2(acc0[14], t00, q7.x, acc0[14]); FMA2(acc1[14], t11, q7.x, acc1[14]);
            FMA2(acc0[15], t00, q7.y, acc0[15]); FMA2(acc1[15], t11, q7.y, acc1[15]);
        }

        __syncthreads();                 // all warps done reading buf
        if (ch + 2 < NCH) {
            STAGE(ch + 2);               // refill the buffer just drained
            CP_WAIT(1);                  // chunk ch+1 complete
        } else {
            CP_WAIT(0);
        }
        __syncthreads();                 // staged data visible
    }

    // ---- epilogue: 2 rows x 32 cols per thread ----
    size_t r0 = (size_t)cta * ROWS + tid;
    float4* o0 = (float4*)(out + r0 * ZDIM);
    float4* o1 = (float4*)(out + (r0 + 128) * ZDIM);
    #pragma unroll
    for (int q = 0; q < 8; q++) {
        float4 v;
        UNPACK2(v.x, v.y, acc0[2 * q]);
        UNPACK2(v.z, v.w, acc0[2 * q + 1]);
        o0[q] = v;
    }
    #pragma unroll
    for (int q = 0; q < 8; q++) {
        float4 v;
        UNPACK2(v.x, v.y, acc1[2 * q]);
        UNPACK2(v.z, v.w, acc1[2 * q + 1]);
        o1[q] = v;
    }
}

// ---------------- launch ----------------------------------------------------
extern "C" void kernel_launch(void* const* d_in, const int* in_sizes, int n_in,
                              void* d_out, int out_size) {
    (void)in_sizes; (void)n_in; (void)out_size;
    const float* z    = (const float*)d_in[0];  // [65536, 32]
    const float* Xi   = (const float*)d_in[1];  // [6545, 32]
    const float* mask = (const float*)d_in[2];  // [6545, 32]
    // d_in[3] (z_mean) and d_in[4] (z_std) are unused by the reference.
    float* out = (float*)d_out;                 // [65536, 32]

    prep_kernel<<<833, 256>>>(Xi, mask);        // xi premask + idx table

    (void)cudaFuncSetAttribute(sindy_kernel,
                               cudaFuncAttributeMaxDynamicSharedMemorySize,
                               SMEM_TOTAL);
    sindy_kernel<<<65536 / ROWS, THREADS, SMEM_TOTAL>>>(z, out);
}